// round 13
// baseline (speedup 1.0000x reference)
#include <cuda_runtime.h>
#include <cstdint>

// out[o,m,n] = sum_{kh,j} w0[o,kh,j] * S[m, n+kh, j]       (n >= 1)
// out[o,m,0] = sum_{kh,j} w0[o,kh,j] * S0[m, kh, j]
// Sg (dup-pair u64): row r in [0,63] = S rows, [64,72] = S0 rows.

__device__ __align__(16) uint64_t Sg[56 * 14 * 80];

__device__ __forceinline__ uint64_t pack2(float s) {
    uint64_t r;
    unsigned u = __float_as_uint(s);
    asm("mov.b64 %0, {%1, %1};" : "=l"(r) : "r"(u));
    return r;
}
__device__ __forceinline__ void ffma2(uint64_t& d, uint64_t a, uint64_t b) {
    asm("fma.rn.f32x2 %0, %1, %2, %0;" : "+l"(d) : "l"(a), "l"(b));
}
__device__ __forceinline__ void addf2(uint64_t& d, uint64_t a) {
    asm("add.rn.f32x2 %0, %0, %1;" : "+l"(d) : "l"(a));
}
__device__ __forceinline__ float2 unpack2(uint64_t v) {
    unsigned lo, hi;
    asm("mov.b64 {%0, %1}, %2;" : "=r"(lo), "=r"(hi) : "l"(v));
    return make_float2(__uint_as_float(lo), __uint_as_float(hi));
}

// ───────────── Kernel 1: build S (dup-pair output) ─────────────
#define XP 68
__global__ __launch_bounds__(160)
void build_S_kernel(const float* __restrict__ x, const float* __restrict__ w1)
{
    __shared__ float xp[24 * XP];   // xp[i][h+5] = x[i,m,h], pads zero
    __shared__ float w1s[24 * 28];
    const int m = blockIdx.x, jg = blockIdx.y, tid = threadIdx.x;

    for (int t = tid; t < 24 * XP; t += 160) xp[t] = 0.0f;
    for (int t = tid; t < 24 * 28; t += 160) w1s[t] = w1[t];
    __syncthreads();
    for (int t = tid; t < 24 * 56; t += 160) {
        const int i = t / 56, h = t % 56;
        xp[i * XP + 5 + h] = x[i * 3136 + m * 56 + h];
    }
    __syncthreads();

    if (tid < 146) {
        const int j = jg * 2 + tid / 73;
        const int r = tid % 73;
        float a0 = 0.f, a1 = 0.f, a2 = 0.f, a3 = 0.f;
        if (r < 64) {
            #pragma unroll
            for (int i = 0; i < 24; i += 2) {
                a0 = fmaf(xp[i * XP + r + 1],     w1s[i * 28 + j],          a0);
                a1 = fmaf(xp[i * XP + r],         w1s[i * 28 + 14 + j],     a1);
                a2 = fmaf(xp[(i+1) * XP + r + 1], w1s[(i+1) * 28 + j],      a2);
                a3 = fmaf(xp[(i+1) * XP + r],     w1s[(i+1) * 28 + 14 + j], a3);
            }
        } else {
            const int kh = r - 64;
            if (kh >= 4) {
                #pragma unroll
                for (int i = 0; i < 24; i += 2) {
                    a0 = fmaf(xp[i * XP + kh + 1],     w1s[i * 28 + j],     a0);
                    a2 = fmaf(xp[(i+1) * XP + kh + 1], w1s[(i+1) * 28 + j], a2);
                }
            }
            if (kh <= 4) {
                #pragma unroll
                for (int i = 0; i < 24; i += 2) {
                    a1 = fmaf(xp[i * XP + kh + 56],     w1s[i * 28 + 14 + j],     a1);
                    a3 = fmaf(xp[(i+1) * XP + kh + 56], w1s[(i+1) * 28 + 14 + j], a3);
                }
            }
        }
        Sg[(m * 14 + j) * 80 + r] = pack2((a0 + a2) + (a1 + a3));
    }
}

// ───────────── Kernel 2: balanced contraction ─────────────
// grid (56 m, 3 og of 32 o, 2 nh of 28 n), block 448 = jh(2) × npq(14) × ow(16).
// Thread: 2 o × 2 n × 7 j (jh half) × 9 kh. 150k threads, ~32 warps/SM.
// Per j: 5 LDS.128 (s rows n0..n0+9) + 9 LDS.64 (w) + 18 FFMA2.
#define WSTR 34
__global__ __launch_bounds__(448, 2)
void contract_kernel(const float* __restrict__ w0, float* __restrict__ out)
{
    __shared__ __align__(16) uint64_t Sd[14 * 80];     // dup-pair S: 8.96 KB
    __shared__ __align__(16) float w0s[126 * WSTR];    // [k][32 o]: 17.1 KB
    __shared__ __align__(16) uint64_t red[224 * 2];    // jh partials: 3.6 KB

    const int m   = blockIdx.x;
    const int og  = blockIdx.y;          // 0..2
    const int nh  = blockIdx.z;          // 0..1
    const int tid = threadIdx.x;

    // stage Sd (560 ulonglong2, coalesced)
    {
        const ulonglong2* __restrict__ src =
            reinterpret_cast<const ulonglong2*>(Sg + m * 1120);
        ulonglong2* dst = reinterpret_cast<ulonglong2*>(Sd);
        for (int t = tid; t < 560; t += 448) dst[t] = src[t];
    }
    // stage w0: coalesced float2 LDG + transpose STS
    {
        const float2* __restrict__ w2 =
            reinterpret_cast<const float2*>(w0 + og * 32 * 126);
        for (int t = tid; t < 32 * 63; t += 448) {
            const int o  = t / 63;
            const int kk = t % 63;
            const float2 v = w2[t];
            w0s[(2 * kk)     * WSTR + o] = v.x;
            w0s[(2 * kk + 1) * WSTR + o] = v.y;
        }
    }
    __syncthreads();

    const int ow  = tid & 15;            // 0..15 -> o pair (o = 2ow, 2ow+1)
    const int npq = (tid >> 4) % 14;     // 0..13 -> n pair
    const int jh  = tid / 224;           // 0..1  -> j half
    const int n0  = nh * 28 + 2 * npq;

    uint64_t accA = 0, accB = 0;         // n0, n0+1

    #pragma unroll
    for (int j = 0; j < 7; j++) {
        const int jj = jh * 7 + j;
        // s rows n0..n0+9 as 5 LDS.128 (Sd dup-pair, 16B aligned since n0 even)
        const ulonglong2* __restrict__ sv =
            reinterpret_cast<const ulonglong2*>(Sd + jj * 80 + n0);
        uint64_t sw[10];
        #pragma unroll
        for (int d = 0; d < 5; d++) {
            const ulonglong2 p = sv[d];
            sw[2 * d] = p.x;  sw[2 * d + 1] = p.y;
        }
        uint64_t wr[9];
        #pragma unroll
        for (int kh = 0; kh < 9; kh++)
            wr[kh] = *reinterpret_cast<const uint64_t*>(
                w0s + (kh * 14 + jj) * WSTR + ow * 2);

        #pragma unroll
        for (int kh = 0; kh < 9; kh++) {
            ffma2(accA, wr[kh], sw[kh]);        // n0 (patched below if n0==0)
            ffma2(accB, wr[kh], sw[kh + 1]);    // n0+1
        }
    }

    // n==0 wraparound: redo accA from S0 rows (64..72); 32 threads per nh==0 block
    if (n0 == 0) {
        accA = 0;
        #pragma unroll
        for (int j = 0; j < 7; j++) {
            const int jj = jh * 7 + j;
            #pragma unroll
            for (int kh = 0; kh < 9; kh++) {
                const uint64_t s = Sd[jj * 80 + 64 + kh];
                const uint64_t w = *reinterpret_cast<const uint64_t*>(
                    w0s + (kh * 14 + jj) * WSTR + ow * 2);
                ffma2(accA, w, s);
            }
        }
    }

    const int rr = tid % 224;
    if (jh == 1) {
        red[rr * 2]     = accA;
        red[rr * 2 + 1] = accB;
    }
    __syncthreads();

    if (jh == 0) {
        addf2(accA, red[rr * 2]);
        addf2(accB, red[rr * 2 + 1]);

        const float2 uA = unpack2(accA);     // (o0, o0+1) at n0
        const float2 uB = unpack2(accB);     // (o0, o0+1) at n0+1
        const int o0 = og * 32 + ow * 2;
        float* op = out + m * 56 + n0;
        *reinterpret_cast<float2*>(op + (o0 + 0) * 3136) = make_float2(uA.x, uB.x);
        *reinterpret_cast<float2*>(op + (o0 + 1) * 3136) = make_float2(uA.y, uB.y);
    }
}

extern "C" void kernel_launch(void* const* d_in, const int* in_sizes, int n_in,
                              void* d_out, int out_size)
{
    const float* x = (const float*)d_in[0];
    const float* w0;
    const float* w1;
    if (in_sizes[1] == 12096) { w0 = (const float*)d_in[1]; w1 = (const float*)d_in[2]; }
    else                      { w0 = (const float*)d_in[2]; w1 = (const float*)d_in[1]; }
    float* out = (float*)d_out;

    build_S_kernel<<<dim3(56, 7), 160>>>(x, w1);
    contract_kernel<<<dim3(56, 3, 2), 448>>>(w0, out);
}

// round 14
// speedup vs baseline: 1.0783x; 1.0783x over previous
#include <cuda_runtime.h>
#include <cstdint>

// out[o,m,n] = sum_{kh,j} w0[o,kh,j] * S[m, n+kh, j]       (n >= 1)
// out[o,m,0] = sum_{kh,j} w0[o,kh,j] * S0[m, kh, j]
// Sg (scalar f32): row r in [0,63] = S rows, [64,72] = S0 rows.
//   Sg[((m*14 + j)*80) + r]

__device__ __align__(16) float Sg[56 * 14 * 80];

// ───────────── Kernel 1: build S ─────────────
#define XP 68
__global__ __launch_bounds__(160)
void build_S_kernel(const float* __restrict__ x, const float* __restrict__ w1)
{
    __shared__ float xp[24 * XP];   // xp[i][h+5] = x[i,m,h], pads zero
    __shared__ float w1s[24 * 28];
    const int m = blockIdx.x, jg = blockIdx.y, tid = threadIdx.x;

    for (int t = tid; t < 24 * XP; t += 160) xp[t] = 0.0f;
    for (int t = tid; t < 24 * 28; t += 160) w1s[t] = w1[t];
    __syncthreads();
    for (int t = tid; t < 24 * 56; t += 160) {
        const int i = t / 56, h = t % 56;
        xp[i * XP + 5 + h] = x[i * 3136 + m * 56 + h];
    }
    __syncthreads();

    if (tid < 146) {
        const int j = jg * 2 + tid / 73;
        const int r = tid % 73;
        float a0 = 0.f, a1 = 0.f, a2 = 0.f, a3 = 0.f;
        if (r < 64) {
            #pragma unroll
            for (int i = 0; i < 24; i += 2) {
                a0 = fmaf(xp[i * XP + r + 1],     w1s[i * 28 + j],          a0);
                a1 = fmaf(xp[i * XP + r],         w1s[i * 28 + 14 + j],     a1);
                a2 = fmaf(xp[(i+1) * XP + r + 1], w1s[(i+1) * 28 + j],      a2);
                a3 = fmaf(xp[(i+1) * XP + r],     w1s[(i+1) * 28 + 14 + j], a3);
            }
        } else {
            const int kh = r - 64;
            if (kh >= 4) {
                #pragma unroll
                for (int i = 0; i < 24; i += 2) {
                    a0 = fmaf(xp[i * XP + kh + 1],     w1s[i * 28 + j],     a0);
                    a2 = fmaf(xp[(i+1) * XP + kh + 1], w1s[(i+1) * 28 + j], a2);
                }
            }
            if (kh <= 4) {
                #pragma unroll
                for (int i = 0; i < 24; i += 2) {
                    a1 = fmaf(xp[i * XP + kh + 56],     w1s[i * 28 + 14 + j],     a1);
                    a3 = fmaf(xp[(i+1) * XP + kh + 56], w1s[(i+1) * 28 + 14 + j], a3);
                }
            }
        }
        Sg[(m * 14 + j) * 80 + r] = (a0 + a2) + (a1 + a3);
    }
}

// ───────────── Kernel 2: balanced scalar contraction ─────────────
// grid (56 m, 6 og of 16 o, 2 nh), block 224: ow = tid&7, jh = bit3, np = tid>>4.
// Thread: 2 o × 2 n × 7 j × 9 kh (jh splits j). Per j: 5 LDS.64 s + 9 LDS.64 w + 36 FFMA.
// jh halves combined in-warp via shfl_xor(8). 150k threads ≈ 32 warps/SM.
#define WSTR 18
__global__ __launch_bounds__(224, 5)
void contract_kernel(const float* __restrict__ w0, float* __restrict__ out)
{
    __shared__ __align__(16) float Ss[14 * 80];        // 4.5 KB scalar S
    __shared__ __align__(16) float w0s[126 * WSTR];    // 9.1 KB [k][16 o]

    const int m   = blockIdx.x;
    const int og  = blockIdx.y;          // 0..5
    const int nh  = blockIdx.z;          // 0..1
    const int tid = threadIdx.x;

    // stage Ss: 280 float4, coalesced
    {
        const float4* __restrict__ src = reinterpret_cast<const float4*>(Sg + m * 1120);
        float4* dst = reinterpret_cast<float4*>(Ss);
        for (int t = tid; t < 280; t += 224) dst[t] = src[t];
    }
    // stage w0: coalesced float2 LDG + transpose STS (one-time, small)
    {
        const float2* __restrict__ w2 =
            reinterpret_cast<const float2*>(w0 + og * 16 * 126);
        for (int t = tid; t < 16 * 63; t += 224) {     // o = t/63, kk = t%63
            const int o  = t / 63;
            const int kk = t % 63;
            const float2 v = w2[t];
            w0s[(2 * kk)     * WSTR + o] = v.x;
            w0s[(2 * kk + 1) * WSTR + o] = v.y;
        }
    }
    __syncthreads();

    const int ow = tid & 7;              // o pair: o = og*16 + 2ow (+1)
    const int jh = (tid >> 3) & 1;       // j half (lane bit 3)
    const int np = tid >> 4;             // 0..13 -> n pair
    const int n0 = nh * 28 + 2 * np;

    const float2* __restrict__ wv2 = reinterpret_cast<const float2*>(w0s);

    float a00 = 0.f, a01 = 0.f, a10 = 0.f, a11 = 0.f;

    #pragma unroll
    for (int j = 0; j < 7; j++) {
        const int jj = jh * 7 + j;
        // s window rows n0..n0+9, 5 x LDS.64 (8B aligned: jj*80+n0 even)
        const float2* __restrict__ sv =
            reinterpret_cast<const float2*>(Ss + jj * 80 + n0);
        float s[10];
        #pragma unroll
        for (int d = 0; d < 5; d++) {
            const float2 p = sv[d];
            s[2 * d] = p.x;  s[2 * d + 1] = p.y;
        }
        float2 w[9];
        #pragma unroll
        for (int kh = 0; kh < 9; kh++)
            w[kh] = wv2[(kh * 14 + jj) * 9 + ow];

        #pragma unroll
        for (int kh = 0; kh < 9; kh++) {
            a00 = fmaf(w[kh].x, s[kh],     a00);
            a01 = fmaf(w[kh].x, s[kh + 1], a01);
            a10 = fmaf(w[kh].y, s[kh],     a10);
            a11 = fmaf(w[kh].y, s[kh + 1], a11);
        }
    }

    // n==0 wraparound: recompute the n0 column from S0 rows (64..72)
    if (n0 == 0) {
        a00 = 0.f;  a10 = 0.f;
        #pragma unroll
        for (int j = 0; j < 7; j++) {
            const int jj = jh * 7 + j;
            #pragma unroll
            for (int kh = 0; kh < 9; kh++) {
                const float  s0 = Ss[jj * 80 + 64 + kh];
                const float2 w  = wv2[(kh * 14 + jj) * 9 + ow];
                a00 = fmaf(w.x, s0, a00);
                a10 = fmaf(w.y, s0, a10);
            }
        }
    }

    // combine jh halves in-warp (partner differs in lane bit 3)
    a00 += __shfl_xor_sync(0xffffffffu, a00, 8);
    a01 += __shfl_xor_sync(0xffffffffu, a01, 8);
    a10 += __shfl_xor_sync(0xffffffffu, a10, 8);
    a11 += __shfl_xor_sync(0xffffffffu, a11, 8);

    if (jh == 0) {
        const int o0 = og * 16 + ow * 2;
        float* op = out + m * 56 + n0;
        *reinterpret_cast<float2*>(op + o0 * 3136)       = make_float2(a00, a01);
        *reinterpret_cast<float2*>(op + (o0 + 1) * 3136) = make_float2(a10, a11);
    }
}

extern "C" void kernel_launch(void* const* d_in, const int* in_sizes, int n_in,
                              void* d_out, int out_size)
{
    const float* x = (const float*)d_in[0];
    const float* w0;
    const float* w1;
    if (in_sizes[1] == 12096) { w0 = (const float*)d_in[1]; w1 = (const float*)d_in[2]; }
    else                      { w0 = (const float*)d_in[2]; w1 = (const float*)d_in[1]; }
    float* out = (float*)d_out;

    build_S_kernel<<<dim3(56, 7), 160>>>(x, w1);
    contract_kernel<<<dim3(56, 6, 2), 224>>>(w0, out);
}

// round 15
// speedup vs baseline: 1.1822x; 1.0964x over previous
#include <cuda_runtime.h>
#include <cstdint>

// out[o, m*56+n] = sum_k W[o,k] * T[m][k][n],  k = kh*14 + j  (126)
//   T[m][k][n] = S[m, n+kh, j]  for n>=1;  T[m][k][0] = S0[m, kh, j]  (wrap folded in)
//   S[m,h',j] rows r=0..63 (r=h'+... zero-padded), S0 rows appended at r=64..72.
// 3xTF32: W,T split hi/lo; C += Al*Bh + Ah*Bl + Ah*Bh  (fp32-grade accuracy).

__device__ __align__(16) float Tg_hi[56 * 126 * 64];   // [m][k][n], n stride 64
__device__ __align__(16) float Tg_lo[56 * 126 * 64];
__device__ __align__(16) float Wg_hi[96 * 126];
__device__ __align__(16) float Wg_lo[96 * 126];

__device__ __forceinline__ void tf32_split(float s, float& hi, float& lo) {
    uint32_t h;
    asm("cvt.rna.tf32.f32 %0, %1;" : "=r"(h) : "f"(s));
    hi = __uint_as_float(h);
    lo = s - hi;
}

__device__ __forceinline__ void mma_tf32(float c[4],
                                         uint32_t a0, uint32_t a1, uint32_t a2, uint32_t a3,
                                         uint32_t b0, uint32_t b1) {
    asm volatile(
        "mma.sync.aligned.m16n8k8.row.col.f32.tf32.tf32.f32 "
        "{%0,%1,%2,%3}, {%4,%5,%6,%7}, {%8,%9}, {%0,%1,%2,%3};"
        : "+f"(c[0]), "+f"(c[1]), "+f"(c[2]), "+f"(c[3])
        : "r"(a0), "r"(a1), "r"(a2), "r"(a3), "r"(b0), "r"(b1));
}

// ───────────── Kernel 1: build S, emit T hi/lo (+ W hi/lo in block 112) ─────────────
#define XP 68
__global__ __launch_bounds__(256)
void build_T_kernel(const float* __restrict__ x,
                    const float* __restrict__ w0,
                    const float* __restrict__ w1)
{
    const int b = blockIdx.x;
    const int tid = threadIdx.x;

    if (b == 112) {       // w0 -> tf32 hi/lo
        for (int t = tid; t < 96 * 126; t += 256) {
            float hi, lo;
            tf32_split(w0[t], hi, lo);
            Wg_hi[t] = hi;
            Wg_lo[t] = lo;
        }
        return;
    }

    const int m    = b >> 1;
    const int half = b & 1;          // n range: half*32 .. half*32+31

    __shared__ float xp[24 * XP];    // xp[i][h+5] = x[i,m,h], pads zero
    __shared__ float w1s[24 * 28];
    __shared__ float Ss[14 * 80];    // rows 0..63 = S, 64..72 = S0

    for (int t = tid; t < 24 * XP; t += 256) xp[t] = 0.0f;
    for (int t = tid; t < 24 * 28; t += 256) w1s[t] = w1[t];
    __syncthreads();
    for (int t = tid; t < 24 * 56; t += 256) {
        const int i = t / 56, h = t % 56;
        xp[i * XP + 5 + h] = x[i * 3136 + m * 56 + h];
    }
    __syncthreads();

    for (int it = tid; it < 14 * 73; it += 256) {
        const int j = it / 73;
        const int r = it % 73;
        float a0 = 0.f, a1 = 0.f, a2 = 0.f, a3 = 0.f;
        if (r < 64) {
            #pragma unroll
            for (int i = 0; i < 24; i += 2) {
                a0 = fmaf(xp[i * XP + r + 1],     w1s[i * 28 + j],          a0);
                a1 = fmaf(xp[i * XP + r],         w1s[i * 28 + 14 + j],     a1);
                a2 = fmaf(xp[(i+1) * XP + r + 1], w1s[(i+1) * 28 + j],      a2);
                a3 = fmaf(xp[(i+1) * XP + r],     w1s[(i+1) * 28 + 14 + j], a3);
            }
        } else {
            const int kh = r - 64;
            if (kh >= 4) {
                #pragma unroll
                for (int i = 0; i < 24; i += 2) {
                    a0 = fmaf(xp[i * XP + kh + 1],     w1s[i * 28 + j],     a0);
                    a2 = fmaf(xp[(i+1) * XP + kh + 1], w1s[(i+1) * 28 + j], a2);
                }
            }
            if (kh <= 4) {
                #pragma unroll
                for (int i = 0; i < 24; i += 2) {
                    a1 = fmaf(xp[i * XP + kh + 56],     w1s[i * 28 + 14 + j],     a1);
                    a3 = fmaf(xp[(i+1) * XP + kh + 56], w1s[(i+1) * 28 + 14 + j], a3);
                }
            }
        }
        Ss[j * 80 + r] = (a0 + a2) + (a1 + a3);
    }
    __syncthreads();

    // T gather + split: 126 k × 32 n (this half)
    float* __restrict__ th = Tg_hi + m * 126 * 64;
    float* __restrict__ tl = Tg_lo + m * 126 * 64;
    for (int idx = tid; idx < 126 * 32; idx += 256) {
        const int k  = idx >> 5;
        const int n  = half * 32 + (idx & 31);
        const int j  = k % 14;
        const int kh = k / 14;
        const int r  = (n == 0) ? (64 + kh) : (n + kh);   // n in 1..63: r <= 71, defined
        float hi, lo;
        tf32_split(Ss[j * 80 + r], hi, lo);
        th[k * 64 + n] = hi;
        tl[k * 64 + n] = lo;
    }
}

// ───────────── Kernel 2: 3xTF32 tensor-core contraction ─────────────
// grid (56 m, 6 og of 16 o), 224 thr = 7 warps; warp w -> n-tile n0 = 8w.
// smem (dynamic): Th[126*72], Tl[126*72], Wh[16*132], Wl[16*132]
#define TSTR 72
#define WSTR2 132
#define SM_TH 0
#define SM_TL (126 * TSTR)
#define SM_WH (2 * 126 * TSTR)
#define SM_WL (2 * 126 * TSTR + 16 * WSTR2)
#define SMEM_FLOATS (2 * 126 * TSTR + 2 * 16 * WSTR2)

__global__ __launch_bounds__(224, 2)
void contract_mma_kernel(float* __restrict__ out)
{
    extern __shared__ float sm[];
    const int m   = blockIdx.x;
    const int og  = blockIdx.y;
    const int tid = threadIdx.x;

    // stage T hi/lo: 2016 float4 each, restride 64 -> 72
    {
        const float4* __restrict__ src_h =
            reinterpret_cast<const float4*>(Tg_hi + m * 126 * 64);
        const float4* __restrict__ src_l =
            reinterpret_cast<const float4*>(Tg_lo + m * 126 * 64);
        for (int t = tid; t < 126 * 16; t += 224) {
            const int k = t >> 4, c = t & 15;
            reinterpret_cast<float4*>(sm + SM_TH + k * TSTR)[c] = src_h[t];
            reinterpret_cast<float4*>(sm + SM_TL + k * TSTR)[c] = src_l[t];
        }
    }
    // stage W hi/lo: 16 o rows, restride 126 -> 132
    for (int t = tid; t < 16 * 126; t += 224) {
        const int ol = t / 126, k = t % 126;
        sm[SM_WH + ol * WSTR2 + k] = Wg_hi[(og * 16 + ol) * 126 + k];
        sm[SM_WL + ol * WSTR2 + k] = Wg_lo[(og * 16 + ol) * 126 + k];
    }
    __syncthreads();

    const uint32_t* __restrict__ ThU = reinterpret_cast<const uint32_t*>(sm + SM_TH);
    const uint32_t* __restrict__ TlU = reinterpret_cast<const uint32_t*>(sm + SM_TL);
    const uint32_t* __restrict__ WhU = reinterpret_cast<const uint32_t*>(sm + SM_WH);
    const uint32_t* __restrict__ WlU = reinterpret_cast<const uint32_t*>(sm + SM_WL);

    const int wid  = tid >> 5;       // 0..6 -> n0 = 8*wid
    const int lane = tid & 31;
    const int g = lane >> 2;         // 0..7
    const int t4 = lane & 3;         // 0..3
    const int n0 = wid * 8;

    float c[4] = {0.f, 0.f, 0.f, 0.f};

    #pragma unroll
    for (int ks = 0; ks < 16; ks++) {
        const int kA = ks * 8 + t4;                 // A col / B row (hi bits of k-step)
        const int aI0 = g * WSTR2 + kA;
        const int aI1 = (g + 8) * WSTR2 + kA;
        const uint32_t ah0 = WhU[aI0],     ah1 = WhU[aI1];
        const uint32_t ah2 = WhU[aI0 + 4], ah3 = WhU[aI1 + 4];
        const uint32_t al0 = WlU[aI0],     al1 = WlU[aI1];
        const uint32_t al2 = WlU[aI0 + 4], al3 = WlU[aI1 + 4];

        const int bI0 = kA * TSTR + n0 + g;
        const int bI1 = (kA + 4) * TSTR + n0 + g;
        const uint32_t bh0 = ThU[bI0], bh1 = ThU[bI1];
        const uint32_t bl0 = TlU[bI0], bl1 = TlU[bI1];

        mma_tf32(c, al0, al1, al2, al3, bh0, bh1);  // Alo * Bhi
        mma_tf32(c, ah0, ah1, ah2, ah3, bl0, bl1);  // Ahi * Blo
        mma_tf32(c, ah0, ah1, ah2, ah3, bh0, bh1);  // Ahi * Bhi
    }

    // C layout: c0:(g, 2t), c1:(g, 2t+1), c2:(g+8, 2t), c3:(g+8, 2t+1)
    const int o0  = og * 16;
    const int col = m * 56 + n0 + 2 * t4;
    *reinterpret_cast<float2*>(out + (o0 + g)     * 3136 + col) = make_float2(c[0], c[1]);
    *reinterpret_cast<float2*>(out + (o0 + g + 8) * 3136 + col) = make_float2(c[2], c[3]);
}

extern "C" void kernel_launch(void* const* d_in, const int* in_sizes, int n_in,
                              void* d_out, int out_size)
{
    const float* x = (const float*)d_in[0];
    const float* w0;
    const float* w1;
    if (in_sizes[1] == 12096) { w0 = (const float*)d_in[1]; w1 = (const float*)d_in[2]; }
    else                      { w0 = (const float*)d_in[2]; w1 = (const float*)d_in[1]; }
    float* out = (float*)d_out;

    static const size_t smem_bytes = SMEM_FLOATS * sizeof(float);   // 89,472 B
    cudaFuncSetAttribute(contract_mma_kernel,
                         cudaFuncAttributeMaxDynamicSharedMemorySize, (int)smem_bytes);

    build_T_kernel<<<113, 256>>>(x, w0, w1);
    contract_mma_kernel<<<dim3(56, 6), 224, smem_bytes>>>(out);
}

// round 16
// speedup vs baseline: 1.3283x; 1.1235x over previous
#include <cuda_runtime.h>
#include <cstdint>

// out[o, m*56+n] = sum_k W[o,k] * T[m][k][n],  k = kh*14 + j  (126, padded to 128)
//   T[m][k][n] = S[m, n+kh, j]  (n>=1);  T[m][k][0] = S0[m, kh, j]  (wrap folded in)
// 3xTF32: W,T split hi/lo; C = Al*Bh + Ah*Bl + Ah*Bh with independent accumulators.

#define KP 128   // padded K (rows 126,127 stay zero: __device__ statics are zero-init,
                 // and no kernel ever writes them)

__device__ __align__(16) float Tg_hi[56 * KP * 64];   // [m][k][n]
__device__ __align__(16) float Tg_lo[56 * KP * 64];
__device__ __align__(16) float Wg_hi[96 * KP];
__device__ __align__(16) float Wg_lo[96 * KP];

__device__ __forceinline__ void tf32_split(float s, float& hi, float& lo) {
    uint32_t h;
    asm("cvt.rna.tf32.f32 %0, %1;" : "=r"(h) : "f"(s));
    hi = __uint_as_float(h);
    lo = s - hi;
}

__device__ __forceinline__ void mma_tf32(float c[4],
                                         uint32_t a0, uint32_t a1, uint32_t a2, uint32_t a3,
                                         uint32_t b0, uint32_t b1) {
    asm volatile(
        "mma.sync.aligned.m16n8k8.row.col.f32.tf32.tf32.f32 "
        "{%0,%1,%2,%3}, {%4,%5,%6,%7}, {%8,%9}, {%0,%1,%2,%3};"
        : "+f"(c[0]), "+f"(c[1]), "+f"(c[2]), "+f"(c[3])
        : "r"(a0), "r"(a1), "r"(a2), "r"(a3), "r"(b0), "r"(b1));
}

// ───────────── Kernel 1: build S, emit T hi/lo (+ W hi/lo in block 112) ─────────────
#define XP 68
__global__ __launch_bounds__(256)
void build_T_kernel(const float* __restrict__ x,
                    const float* __restrict__ w0,
                    const float* __restrict__ w1)
{
    const int b = blockIdx.x;
    const int tid = threadIdx.x;

    if (b == 112) {       // w0 -> tf32 hi/lo (k<126; padding stays zero)
        for (int t = tid; t < 96 * 126; t += 256) {
            const int o = t / 126, k = t % 126;
            float hi, lo;
            tf32_split(w0[t], hi, lo);
            Wg_hi[o * KP + k] = hi;
            Wg_lo[o * KP + k] = lo;
        }
        return;
    }

    const int m    = b >> 1;
    const int half = b & 1;          // n range: half*32 .. half*32+31

    __shared__ float xp[24 * XP];    // xp[i][h+5] = x[i,m,h], pads zero
    __shared__ float w1s[24 * 28];
    __shared__ float Ss[14 * 80];    // rows 0..63 = S, 64..72 = S0

    for (int t = tid; t < 24 * XP; t += 256) xp[t] = 0.0f;
    for (int t = tid; t < 24 * 28; t += 256) w1s[t] = w1[t];
    __syncthreads();
    for (int t = tid; t < 24 * 56; t += 256) {
        const int i = t / 56, h = t % 56;
        xp[i * XP + 5 + h] = x[i * 3136 + m * 56 + h];
    }
    __syncthreads();

    for (int it = tid; it < 14 * 73; it += 256) {
        const int j = it / 73;
        const int r = it % 73;
        float a0 = 0.f, a1 = 0.f, a2 = 0.f, a3 = 0.f;
        if (r < 64) {
            #pragma unroll
            for (int i = 0; i < 24; i += 2) {
                a0 = fmaf(xp[i * XP + r + 1],     w1s[i * 28 + j],          a0);
                a1 = fmaf(xp[i * XP + r],         w1s[i * 28 + 14 + j],     a1);
                a2 = fmaf(xp[(i+1) * XP + r + 1], w1s[(i+1) * 28 + j],      a2);
                a3 = fmaf(xp[(i+1) * XP + r],     w1s[(i+1) * 28 + 14 + j], a3);
            }
        } else {
            const int kh = r - 64;
            if (kh >= 4) {
                #pragma unroll
                for (int i = 0; i < 24; i += 2) {
                    a0 = fmaf(xp[i * XP + kh + 1],     w1s[i * 28 + j],     a0);
                    a2 = fmaf(xp[(i+1) * XP + kh + 1], w1s[(i+1) * 28 + j], a2);
                }
            }
            if (kh <= 4) {
                #pragma unroll
                for (int i = 0; i < 24; i += 2) {
                    a1 = fmaf(xp[i * XP + kh + 56],     w1s[i * 28 + 14 + j],     a1);
                    a3 = fmaf(xp[(i+1) * XP + kh + 56], w1s[(i+1) * 28 + 14 + j], a3);
                }
            }
        }
        Ss[j * 80 + r] = (a0 + a2) + (a1 + a3);
    }
    __syncthreads();

    // T gather + split: 126 k × 32 n (this half); k=126..127 stay zero
    float* __restrict__ th = Tg_hi + m * KP * 64;
    float* __restrict__ tl = Tg_lo + m * KP * 64;
    for (int idx = tid; idx < 126 * 32; idx += 256) {
        const int k  = idx >> 5;
        const int n  = half * 32 + (idx & 31);
        const int j  = k % 14;
        const int kh = k / 14;
        const int r  = (n == 0) ? (64 + kh) : (n + kh);
        float hi, lo;
        tf32_split(Ss[j * 80 + r], hi, lo);
        th[k * 64 + n] = hi;
        tl[k * 64 + n] = lo;
    }
}

// ───────────── Kernel 2: 3xTF32 tensor-core contraction ─────────────
// grid (56 m, 3 og32), block 448 = 14 warps: og2 = w/7 (16 o), ntile = w%7 (8 n).
// smem: Th[128*72], Tl[128*72], Wh[32*132], Wl[32*132] = 107.2 KB
#define TSTR 72
#define WSTR2 132
#define SM_TH 0
#define SM_TL (KP * TSTR)
#define SM_WH (2 * KP * TSTR)
#define SM_WL (2 * KP * TSTR + 32 * WSTR2)
#define SMEM_FLOATS (2 * KP * TSTR + 2 * 32 * WSTR2)

__global__ __launch_bounds__(448)
void contract_mma_kernel(float* __restrict__ out)
{
    extern __shared__ float sm[];
    const int m   = blockIdx.x;
    const int og  = blockIdx.y;          // 0..2 (32 o)
    const int tid = threadIdx.x;

    // stage T hi/lo: 128 rows × 16 float4, restride 64 -> 72
    {
        const float4* __restrict__ src_h =
            reinterpret_cast<const float4*>(Tg_hi + m * KP * 64);
        const float4* __restrict__ src_l =
            reinterpret_cast<const float4*>(Tg_lo + m * KP * 64);
        for (int t = tid; t < KP * 16; t += 448) {
            const int k = t >> 4, c = t & 15;
            reinterpret_cast<float4*>(sm + SM_TH + k * TSTR)[c] = src_h[t];
            reinterpret_cast<float4*>(sm + SM_TL + k * TSTR)[c] = src_l[t];
        }
    }
    // stage W hi/lo: 32 o rows × 128 k, restride 128 -> 132
    for (int t = tid; t < 32 * KP; t += 448) {
        const int ol = t >> 7, k = t & 127;
        sm[SM_WH + ol * WSTR2 + k] = Wg_hi[(og * 32 + ol) * KP + k];
        sm[SM_WL + ol * WSTR2 + k] = Wg_lo[(og * 32 + ol) * KP + k];
    }
    __syncthreads();

    const uint32_t* __restrict__ ThU = reinterpret_cast<const uint32_t*>(sm + SM_TH);
    const uint32_t* __restrict__ TlU = reinterpret_cast<const uint32_t*>(sm + SM_TL);
    const uint32_t* __restrict__ WhU = reinterpret_cast<const uint32_t*>(sm + SM_WH);
    const uint32_t* __restrict__ WlU = reinterpret_cast<const uint32_t*>(sm + SM_WL);

    const int wid  = tid >> 5;           // 0..13
    const int og2  = wid / 7;            // 0..1 -> 16-o half
    const int nt   = wid % 7;            // 0..6 -> n0 = 8*nt
    const int lane = tid & 31;
    const int g  = lane >> 2;            // 0..7
    const int t4 = lane & 3;             // 0..3
    const int n0 = nt * 8;
    const int wbase = og2 * 16 * WSTR2;

    float chh[4] = {0,0,0,0}, clh[4] = {0,0,0,0}, chl[4] = {0,0,0,0};

    // fragment loader for k-step ks
    auto LD = [&](int ks, uint32_t& ah0, uint32_t& ah1, uint32_t& ah2, uint32_t& ah3,
                  uint32_t& al0, uint32_t& al1, uint32_t& al2, uint32_t& al3,
                  uint32_t& bh0, uint32_t& bh1, uint32_t& bl0, uint32_t& bl1) {
        const int kA  = ks * 8 + t4;
        const int aI0 = wbase + g * WSTR2 + kA;
        const int aI1 = wbase + (g + 8) * WSTR2 + kA;
        ah0 = WhU[aI0];     ah1 = WhU[aI1];
        ah2 = WhU[aI0 + 4]; ah3 = WhU[aI1 + 4];
        al0 = WlU[aI0];     al1 = WlU[aI1];
        al2 = WlU[aI0 + 4]; al3 = WlU[aI1 + 4];
        const int bI0 = kA * TSTR + n0 + g;
        const int bI1 = (kA + 4) * TSTR + n0 + g;
        bh0 = ThU[bI0]; bh1 = ThU[bI1];
        bl0 = TlU[bI0]; bl1 = TlU[bI1];
    };

    uint32_t ah0, ah1, ah2, ah3, al0, al1, al2, al3, bh0, bh1, bl0, bl1;
    LD(0, ah0, ah1, ah2, ah3, al0, al1, al2, al3, bh0, bh1, bl0, bl1);

    #pragma unroll
    for (int ks = 0; ks < 16; ks++) {
        uint32_t nah0, nah1, nah2, nah3, nal0, nal1, nal2, nal3, nbh0, nbh1, nbl0, nbl1;
        if (ks < 15)
            LD(ks + 1, nah0, nah1, nah2, nah3, nal0, nal1, nal2, nal3,
               nbh0, nbh1, nbl0, nbl1);

        mma_tf32(clh, al0, al1, al2, al3, bh0, bh1);   // Alo * Bhi
        mma_tf32(chl, ah0, ah1, ah2, ah3, bl0, bl1);   // Ahi * Blo
        mma_tf32(chh, ah0, ah1, ah2, ah3, bh0, bh1);   // Ahi * Bhi

        if (ks < 15) {
            ah0 = nah0; ah1 = nah1; ah2 = nah2; ah3 = nah3;
            al0 = nal0; al1 = nal1; al2 = nal2; al3 = nal3;
            bh0 = nbh0; bh1 = nbh1; bl0 = nbl0; bl1 = nbl1;
        }
    }

    float c[4];
    #pragma unroll
    for (int i = 0; i < 4; i++) c[i] = chh[i] + (clh[i] + chl[i]);

    // C layout: c0:(g, 2t4), c1:(g, 2t4+1), c2:(g+8, 2t4), c3:(g+8, 2t4+1)
    const int o0  = og * 32 + og2 * 16;
    const int col = m * 56 + n0 + 2 * t4;
    *reinterpret_cast<float2*>(out + (o0 + g)     * 3136 + col) = make_float2(c[0], c[1]);
    *reinterpret_cast<float2*>(out + (o0 + g + 8) * 3136 + col) = make_float2(c[2], c[3]);
}

extern "C" void kernel_launch(void* const* d_in, const int* in_sizes, int n_in,
                              void* d_out, int out_size)
{
    const float* x = (const float*)d_in[0];
    const float* w0;
    const float* w1;
    if (in_sizes[1] == 12096) { w0 = (const float*)d_in[1]; w1 = (const float*)d_in[2]; }
    else                      { w0 = (const float*)d_in[2]; w1 = (const float*)d_in[1]; }
    float* out = (float*)d_out;

    static const size_t smem_bytes = SMEM_FLOATS * sizeof(float);   // 107.2 KB
    cudaFuncSetAttribute(contract_mma_kernel,
                         cudaFuncAttributeMaxDynamicSharedMemorySize, (int)smem_bytes);

    build_T_kernel<<<113, 256>>>(x, w0, w1);
    contract_mma_kernel<<<dim3(56, 3), 448, smem_bytes>>>(out);
}

// round 17
// speedup vs baseline: 1.6991x; 1.2792x over previous
#include <cuda_runtime.h>
#include <cstdint>

// Fully fused: out[o, m*56+n] = sum_k W[o,k] * T[m][k][n],  k = kh*14+j (126 -> KP=128)
//   T[m][k][n] = S[m, n+kh, j] (n>=1);  T[m][k][0] = S0[m, kh, j]  (wrap folded in)
//   S built in smem per block; 3xTF32 MMA (C = Ah*Bh + Al*Bh + Ah*Bl).
// grid (56 m, 2 og of 48 o), block 672 = 21 warps (3 o-tiles x 7 n-tiles). One wave.

#define KP    128
#define TSTR  72      // Th/Tl row stride (floats)
#define WSTRW 132     // Wh/Wl row stride (floats)
#define XP    68

// smem layout (floats)
#define SM_TH 0
#define SM_TL (SM_TH + KP * TSTR)            // 9216
#define SM_WH (SM_TL + KP * TSTR)            // 18432
#define SM_WL (SM_WH + 48 * WSTRW)           // 24768
#define SM_XP (SM_WL + 48 * WSTRW)           // 31104
#define SM_W1 (SM_XP + 24 * XP)              // 32736
#define SM_SS (SM_W1 + 24 * 28)              // 33408
#define SMEM_FLOATS (SM_SS + 14 * 80)        // 34528 -> 138,112 B

__device__ __forceinline__ void tf32_split(float s, float& hi, float& lo) {
    uint32_t h;
    asm("cvt.rna.tf32.f32 %0, %1;" : "=r"(h) : "f"(s));
    hi = __uint_as_float(h);
    lo = s - hi;
}

__device__ __forceinline__ void mma_tf32(float c[4],
                                         uint32_t a0, uint32_t a1, uint32_t a2, uint32_t a3,
                                         uint32_t b0, uint32_t b1) {
    asm volatile(
        "mma.sync.aligned.m16n8k8.row.col.f32.tf32.tf32.f32 "
        "{%0,%1,%2,%3}, {%4,%5,%6,%7}, {%8,%9}, {%0,%1,%2,%3};"
        : "+f"(c[0]), "+f"(c[1]), "+f"(c[2]), "+f"(c[3])
        : "r"(a0), "r"(a1), "r"(a2), "r"(a3), "r"(b0), "r"(b1));
}

__global__ __launch_bounds__(672)
void fused_mma_kernel(const float* __restrict__ x,
                      const float* __restrict__ w0,
                      const float* __restrict__ w1,
                      float* __restrict__ out)
{
    extern __shared__ float sm[];
    const int m   = blockIdx.x;
    const int og  = blockIdx.y;          // 0..1 (48 o each)
    const int tid = threadIdx.x;

    // ── Phase A: zeros + staged inputs ──
    for (int t = tid; t < 24 * XP; t += 672) sm[SM_XP + t] = 0.0f;
    // zero T pad rows (k = 126,127) and W pad cols (k = 126,127)
    for (int t = tid; t < 2 * TSTR; t += 672) {
        sm[SM_TH + 126 * TSTR + t] = 0.0f;
        sm[SM_TL + 126 * TSTR + t] = 0.0f;
    }
    for (int t = tid; t < 48 * 2; t += 672) {
        const int o = t >> 1, k = 126 + (t & 1);
        sm[SM_WH + o * WSTRW + k] = 0.0f;
        sm[SM_WL + o * WSTRW + k] = 0.0f;
    }
    if (tid < 672) sm[SM_W1 + tid] = w1[tid];
    // w0 slice: 48 o x 126 k, coalesced float2, split hi/lo
    {
        const float2* __restrict__ w2 =
            reinterpret_cast<const float2*>(w0 + og * 48 * 126);
        for (int t = tid; t < 48 * 63; t += 672) {
            const int o  = t / 63;
            const int kk = t % 63;
            const float2 v = w2[t];
            float h0, l0, h1, l1;
            tf32_split(v.x, h0, l0);
            tf32_split(v.y, h1, l1);
            sm[SM_WH + o * WSTRW + 2 * kk]     = h0;
            sm[SM_WL + o * WSTRW + 2 * kk]     = l0;
            sm[SM_WH + o * WSTRW + 2 * kk + 1] = h1;
            sm[SM_WL + o * WSTRW + 2 * kk + 1] = l1;
        }
    }
    __syncthreads();            // xp zeros visible
    // x slice: 24 x 56 as float4 (16B aligned: m*56*4 % 16 == 0)
    {
        const float4* __restrict__ x4 = reinterpret_cast<const float4*>(x + m * 56);
        for (int t = tid; t < 24 * 14; t += 672) {
            const int i = t / 14, c = t % 14;
            const float4 v = x4[i * 784 + c];
            float* dst = sm + SM_XP + i * XP + 5 + c * 4;
            dst[0] = v.x; dst[1] = v.y; dst[2] = v.z; dst[3] = v.w;
        }
    }
    __syncthreads();

    // ── Phase B: build S (14 j x 73 r) ──
    for (int it = tid; it < 14 * 73; it += 672) {
        const int j = it / 73;
        const int r = it % 73;
        const float* xp  = sm + SM_XP;
        const float* w1s = sm + SM_W1;
        float a0 = 0.f, a1 = 0.f, a2 = 0.f, a3 = 0.f;
        if (r < 64) {
            #pragma unroll
            for (int i = 0; i < 24; i += 2) {
                a0 = fmaf(xp[i * XP + r + 1],     w1s[i * 28 + j],          a0);
                a1 = fmaf(xp[i * XP + r],         w1s[i * 28 + 14 + j],     a1);
                a2 = fmaf(xp[(i+1) * XP + r + 1], w1s[(i+1) * 28 + j],      a2);
                a3 = fmaf(xp[(i+1) * XP + r],     w1s[(i+1) * 28 + 14 + j], a3);
            }
        } else {
            const int kh = r - 64;
            if (kh >= 4) {
                #pragma unroll
                for (int i = 0; i < 24; i += 2) {
                    a0 = fmaf(xp[i * XP + kh + 1],     w1s[i * 28 + j],     a0);
                    a2 = fmaf(xp[(i+1) * XP + kh + 1], w1s[(i+1) * 28 + j], a2);
                }
            }
            if (kh <= 4) {
                #pragma unroll
                for (int i = 0; i < 24; i += 2) {
                    a1 = fmaf(xp[i * XP + kh + 56],     w1s[i * 28 + 14 + j],     a1);
                    a3 = fmaf(xp[(i+1) * XP + kh + 56], w1s[(i+1) * 28 + 14 + j], a3);
                }
            }
        }
        sm[SM_SS + j * 80 + r] = (a0 + a2) + (a1 + a3);
    }
    __syncthreads();

    // ── Phase C: gather + tf32 split into Th/Tl [k][n] (126 x 64) ──
    for (int idx = tid; idx < 126 * 64; idx += 672) {
        const int k  = idx >> 6;
        const int n  = idx & 63;
        const int j  = k % 14;
        const int kh = k / 14;
        const int r  = (n == 0) ? (64 + kh) : (n + kh);
        float hi, lo;
        tf32_split(sm[SM_SS + j * 80 + r], hi, lo);
        sm[SM_TH + k * TSTR + n] = hi;
        sm[SM_TL + k * TSTR + n] = lo;
    }
    __syncthreads();

    // ── Phase D: 3xTF32 MMA, 16 k-steps ──
    const uint32_t* __restrict__ ThU = reinterpret_cast<const uint32_t*>(sm + SM_TH);
    const uint32_t* __restrict__ TlU = reinterpret_cast<const uint32_t*>(sm + SM_TL);
    const uint32_t* __restrict__ WhU = reinterpret_cast<const uint32_t*>(sm + SM_WH);
    const uint32_t* __restrict__ WlU = reinterpret_cast<const uint32_t*>(sm + SM_WL);

    const int wid  = tid >> 5;           // 0..20
    const int ot   = wid / 7;            // 0..2 -> 16-o tile
    const int nt   = wid % 7;            // 0..6 -> n0 = 8*nt
    const int lane = tid & 31;
    const int g  = lane >> 2;            // 0..7
    const int t4 = lane & 3;             // 0..3
    const int n0 = nt * 8;
    const int wbase = ot * 16 * WSTRW;

    float chh[4] = {0,0,0,0}, clh[4] = {0,0,0,0}, chl[4] = {0,0,0,0};

    #pragma unroll
    for (int ks = 0; ks < 16; ks++) {
        const int kA  = ks * 8 + t4;
        const int aI0 = wbase + g * WSTRW + kA;
        const int aI1 = wbase + (g + 8) * WSTRW + kA;
        const uint32_t ah0 = WhU[aI0],     ah1 = WhU[aI1];
        const uint32_t ah2 = WhU[aI0 + 4], ah3 = WhU[aI1 + 4];
        const uint32_t al0 = WlU[aI0],     al1 = WlU[aI1];
        const uint32_t al2 = WlU[aI0 + 4], al3 = WlU[aI1 + 4];

        const int bI0 = kA * TSTR + n0 + g;
        const int bI1 = (kA + 4) * TSTR + n0 + g;
        const uint32_t bh0 = ThU[bI0], bh1 = ThU[bI1];
        const uint32_t bl0 = TlU[bI0], bl1 = TlU[bI1];

        mma_tf32(clh, al0, al1, al2, al3, bh0, bh1);   // Alo * Bhi
        mma_tf32(chl, ah0, ah1, ah2, ah3, bl0, bl1);   // Ahi * Blo
        mma_tf32(chh, ah0, ah1, ah2, ah3, bh0, bh1);   // Ahi * Bhi
    }

    float c[4];
    #pragma unroll
    for (int i = 0; i < 4; i++) c[i] = chh[i] + (clh[i] + chl[i]);

    // ── Phase E: store. c0:(g,2t4) c1:(g,2t4+1) c2:(g+8,2t4) c3:(g+8,2t4+1) ──
    const int o0  = og * 48 + ot * 16;
    const int col = m * 56 + n0 + 2 * t4;
    *reinterpret_cast<float2*>(out + (o0 + g)     * 3136 + col) = make_float2(c[0], c[1]);
    *reinterpret_cast<float2*>(out + (o0 + g + 8) * 3136 + col) = make_float2(c[2], c[3]);
}

extern "C" void kernel_launch(void* const* d_in, const int* in_sizes, int n_in,
                              void* d_out, int out_size)
{
    const float* x = (const float*)d_in[0];
    const float* w0;
    const float* w1;
    if (in_sizes[1] == 12096) { w0 = (const float*)d_in[1]; w1 = (const float*)d_in[2]; }
    else                      { w0 = (const float*)d_in[2]; w1 = (const float*)d_in[1]; }
    float* out = (float*)d_out;

    static const size_t smem_bytes = SMEM_FLOATS * sizeof(float);   // 138,112 B
    cudaFuncSetAttribute(fused_mma_kernel,
                         cudaFuncAttributeMaxDynamicSharedMemorySize, (int)smem_bytes);

    fused_mma_kernel<<<dim3(56, 2), 672, smem_bytes>>>(x, w0, w1, out);
}